// round 11
// baseline (speedup 1.0000x reference)
#include <cuda_runtime.h>
#include <math.h>

#define B_ROWS   2048
#define NL       64
#define NN       16
#define NO       2048
#define ZSTRIDE  80          // NL + NN
#define GRP_B    64          // rows per compute group
#define CHUNK_O  128         // cols per block
#define NTHREADS 256

// ---------------- device scratch (no allocations allowed) ----------------
__device__ int   g_nid[B_ROWS];
__device__ int   g_order[B_ROWS];
__device__ int   g_bucket_base[NN + 1];
__device__ float g_logits[(size_t)B_ROWS * NO];   // 16 MB, indexed by SORTED pos

// ---------------- packed f32x2 helpers (sm_103a FFMA2 via PTX) ------------
__device__ __forceinline__ void ffma2(unsigned long long& acc,
                                      unsigned long long a,
                                      unsigned long long b)
{
    asm("fma.rn.f32x2 %0, %1, %2, %0;" : "+l"(acc) : "l"(a), "l"(b));
}
__device__ __forceinline__ unsigned long long bcast2(float v)
{
    unsigned long long r;
    asm("mov.b64 %0, {%1, %1};" : "=l"(r) : "f"(v));
    return r;
}
__device__ __forceinline__ float2 unpack2(unsigned long long p)
{
    float2 f;
    asm("mov.b64 {%0, %1}, %2;" : "=f"(f.x), "=f"(f.y) : "l"(p));
    return f;
}

// ---------------- kernel 1: per-row argmax of nuisance one-hot + theta ----
__global__ void k_prep(const float* __restrict__ z,
                       const float* __restrict__ px_r,
                       float* __restrict__ theta_out)
{
    int g = blockIdx.x * blockDim.x + threadIdx.x;
    if (g < B_ROWS) {
        const float* p = z + (size_t)g * ZSTRIDE + NL;
        float best = p[0]; int bi = 0;
        #pragma unroll
        for (int i = 1; i < NN; i++) {
            float v = p[i];
            if (v > best) { best = v; bi = i; }   // first-max wins (jnp.argmax)
        }
        g_nid[g] = bi;
    }
    if (g < NO) theta_out[g] = expf(px_r[g]);
}

// ---------------- kernel 2: counting sort by nid ---------------------------
__global__ void k_sort()
{
    __shared__ int cnt[NN];
    __shared__ int offs[NN];
    int t = threadIdx.x;
    if (t < NN) cnt[t] = 0;
    __syncthreads();
    for (int b = t; b < B_ROWS; b += blockDim.x)
        atomicAdd(&cnt[g_nid[b]], 1);
    __syncthreads();
    if (t == 0) {
        int acc = 0;
        for (int i = 0; i < NN; i++) {
            g_bucket_base[i] = acc;
            offs[i] = acc;
            acc += cnt[i];
        }
        g_bucket_base[NN] = acc;
    }
    __syncthreads();
    for (int b = t; b < B_ROWS; b += blockDim.x) {
        int p = atomicAdd(&offs[g_nid[b]], 1);
        g_order[p] = b;
    }
}

// Z tile swizzle: row-major [r][64], float4-group column c4 (0..15) XORed by
// a bit derived from r so that rows r and r+4 (the two ty-groups of a warp)
// land 16 banks apart. Mainloop loads are LDS.128, conflict-free.
__device__ __forceinline__ int zc4(int r, int c4)
{
    return c4 ^ (((r >> 2) & 1) << 2);
}

// ---------------- kernel 3: bucket-resident GEMM --------------------------
// grid = (bucket, ochunk). A_eff = W + S[bucket] staged ONCE per block;
// loop over the bucket's 64-row groups restaging only the 16 KB Z tile.
// logits (sorted-position indexed) = Z0 @ A_eff + offsets[bucket].
// Dynamic smem = 64*64 (Zs) + 64*128 (As) floats = 49152 B exactly.
__global__ __launch_bounds__(NTHREADS)
void k_gemm(const float* __restrict__ z,
            const float* __restrict__ W,
            const float* __restrict__ S,
            const float* __restrict__ offsets)
{
    extern __shared__ float sm[];
    float* Zs = sm;                       // [64][64] row-major, swizzled c4
    float* As = sm + GRP_B * NL;          // [64][128]

    int tid    = threadIdx.x;
    int bucket = blockIdx.x;
    int oc     = blockIdx.y;
    int o0     = oc * CHUNK_O;

    int start = g_bucket_base[bucket];
    int cnt   = g_bucket_base[bucket + 1] - start;
    if (cnt == 0) return;

    int tx = tid & 15;     // col group: cols {tx*4..+3} and {64+tx*4..+3}
    int ty = tid >> 4;     // row group: rows ty*4..+3

    // ---- stage A_eff = W + S[bucket] (64 x 128 floats = 2048 float4) -----
    {
        const float4* W4 = (const float4*)W;
        const float4* S4 = (const float4*)(S + (size_t)bucket * NL * NO);
        int ob4 = o0 >> 2;
        #pragma unroll
        for (int j = 0; j < 8; j++) {
            int e  = tid + j * NTHREADS;   // 0..2047
            int k  = e >> 5;
            int c4 = e & 31;
            float4 w = W4[(size_t)k * (NO / 4) + ob4 + c4];
            float4 s = S4[(size_t)k * (NO / 4) + ob4 + c4];
            ((float4*)(As + k * CHUNK_O))[c4] =
                make_float4(w.x + s.x, w.y + s.y, w.z + s.z, w.w + s.w);
        }
    }

    const float4 offlo = *(const float4*)(offsets + (size_t)bucket * NO + o0 + tx * 4);
    const float4 offhi = *(const float4*)(offsets + (size_t)bucket * NO + o0 + 64 + tx * 4);

    int ngroups = (cnt + GRP_B - 1) >> 6;
    for (int grp = 0; grp < ngroups; grp++) {
        int gs   = start + grp * GRP_B;          // sorted-position base
        int vcnt = min(GRP_B, cnt - grp * GRP_B);

        // ---- stage Z (64 rows x 16 float4 = 1024 float4) ----
        #pragma unroll
        for (int j = 0; j < 4; j++) {
            int e  = tid + j * NTHREADS;   // 0..1023
            int r  = e >> 4;
            int l4 = e & 15;
            float4 v = make_float4(0.f, 0.f, 0.f, 0.f);
            if (r < vcnt) {
                int row = g_order[gs + r];
                v = *(const float4*)(z + (size_t)row * ZSTRIDE + l4 * 4);
            }
            *(float4*)(Zs + r * NL + zc4(r, l4) * 4) = v;
        }
        __syncthreads();    // Zs (and, on grp 0, As) staged

        unsigned long long acc[4][4];
        #pragma unroll
        for (int i = 0; i < 4; i++)
            #pragma unroll
            for (int j = 0; j < 4; j++) acc[i][j] = 0ull;

        #pragma unroll 4
        for (int k4 = 0; k4 < NL; k4 += 4) {
            float4 zq[4];
            #pragma unroll
            for (int i = 0; i < 4; i++) {
                int r = ty * 4 + i;
                zq[i] = *(const float4*)(Zs + r * NL + zc4(r, k4 >> 2) * 4);
            }
            #pragma unroll
            for (int kk = 0; kk < 4; kk++) {
                ulonglong2 a0 = *(const ulonglong2*)(As + (k4 + kk) * CHUNK_O + tx * 4);
                ulonglong2 a1 = *(const ulonglong2*)(As + (k4 + kk) * CHUNK_O + 64 + tx * 4);
                #pragma unroll
                for (int i = 0; i < 4; i++) {
                    unsigned long long zz = bcast2((&zq[i].x)[kk]);
                    ffma2(acc[i][0], zz, a0.x);
                    ffma2(acc[i][1], zz, a0.y);
                    ffma2(acc[i][2], zz, a1.x);
                    ffma2(acc[i][3], zz, a1.y);
                }
            }
        }

        // ---- epilogue: + offsets, dense write at sorted position ---------
        #pragma unroll
        for (int i = 0; i < 4; i++) {
            int r = ty * 4 + i;
            if (r >= vcnt) continue;
            float2 p0 = unpack2(acc[i][0]);
            float2 p1 = unpack2(acc[i][1]);
            float2 p2 = unpack2(acc[i][2]);
            float2 p3 = unpack2(acc[i][3]);
            float* dst = g_logits + (size_t)(gs + r) * NO + o0;
            *(float4*)(dst + tx * 4) =
                make_float4(p0.x + offlo.x, p0.y + offlo.y,
                            p1.x + offlo.z, p1.y + offlo.w);
            *(float4*)(dst + 64 + tx * 4) =
                make_float4(p2.x + offhi.x, p2.y + offhi.y,
                            p3.x + offhi.z, p3.y + offhi.w);
        }
        __syncthreads();    // protect Zs before next group's restage
    }
}

// ---------------- kernel 4: row softmax * size_factor (flash, 2 rows/block)
// Reads sorted row p from g_logits, writes mu[g_order[p]].
__global__ __launch_bounds__(NTHREADS)
void k_softmax(const float* __restrict__ sf, float* __restrict__ mu)
{
    int tid  = threadIdx.x;
    int half = tid >> 7;                 // 0/1: which row of this block
    int t    = tid & 127;                // position within row (float4 units)
    int p    = blockIdx.x * 2 + half;    // sorted position
    int lane = tid & 31;
    int wid  = tid >> 5;                 // 0..7 (warps 0-3 row0, 4-7 row1)

    int orig = g_order[p];

    const float4* src = (const float4*)g_logits + (size_t)p * (NO / 4);
    float4 v[4];
    #pragma unroll
    for (int q = 0; q < 4; q++) v[q] = src[t + q * 128];

    // per-warp max over this thread's 16 values
    float mx = -1e30f;
    #pragma unroll
    for (int q = 0; q < 4; q++)
        mx = fmaxf(mx, fmaxf(fmaxf(v[q].x, v[q].y), fmaxf(v[q].z, v[q].w)));
    #pragma unroll
    for (int o = 16; o; o >>= 1)
        mx = fmaxf(mx, __shfl_xor_sync(0xffffffffu, mx, o));

    // per-warp sum of exp(v - warp_max)
    float e[16];
    float s = 0.f;
    #pragma unroll
    for (int q = 0; q < 4; q++) {
        e[q * 4 + 0] = __expf(v[q].x - mx);
        e[q * 4 + 1] = __expf(v[q].y - mx);
        e[q * 4 + 2] = __expf(v[q].z - mx);
        e[q * 4 + 3] = __expf(v[q].w - mx);
        s += (e[q * 4 + 0] + e[q * 4 + 1]) + (e[q * 4 + 2] + e[q * 4 + 3]);
    }
    #pragma unroll
    for (int o = 16; o; o >>= 1)
        s += __shfl_xor_sync(0xffffffffu, s, o);

    __shared__ float smax[8];
    __shared__ float ssum[8];
    if (lane == 0) { smax[wid] = mx; ssum[wid] = s; }
    __syncthreads();

    int w0 = half * 4;   // this row's warps: w0..w0+3
    float M = fmaxf(fmaxf(smax[w0], smax[w0 + 1]),
                    fmaxf(smax[w0 + 2], smax[w0 + 3]));
    float Ssum = ssum[w0]     * __expf(smax[w0]     - M)
               + ssum[w0 + 1] * __expf(smax[w0 + 1] - M)
               + ssum[w0 + 2] * __expf(smax[w0 + 2] - M)
               + ssum[w0 + 3] * __expf(smax[w0 + 3] - M);

    // rescale warp-local exps: e * exp(mx - M) / Ssum * sf
    float scale = (sf[orig] / Ssum) * __expf(mx - M);

    float4* dst = (float4*)mu + (size_t)orig * (NO / 4);
    #pragma unroll
    for (int q = 0; q < 4; q++)
        dst[t + q * 128] = make_float4(e[q * 4 + 0] * scale, e[q * 4 + 1] * scale,
                                       e[q * 4 + 2] * scale, e[q * 4 + 3] * scale);
}

// -------------------------------------------------------------------------
extern "C" void kernel_launch(void* const* d_in, const int* in_sizes, int n_in,
                              void* d_out, int out_size)
{
    const float* z       = (const float*)d_in[0];
    const float* sf      = (const float*)d_in[1];
    const float* W       = (const float*)d_in[2];
    const float* S       = (const float*)d_in[3];
    const float* offsets = (const float*)d_in[4];
    const float* px_r    = (const float*)d_in[5];
    float* out   = (float*)d_out;
    float* theta = out + (out_size - NO);   // layout: mu[B,NO] then theta[NO]

    k_prep<<<(B_ROWS + NTHREADS - 1) / NTHREADS, NTHREADS>>>(z, px_r, theta);
    k_sort<<<1, NTHREADS>>>();

    size_t smem = (size_t)(GRP_B * NL + NL * CHUNK_O) * sizeof(float);  // 49152 B
    k_gemm<<<dim3(NN, NO / CHUNK_O), NTHREADS, smem>>>(z, W, S, offsets);

    k_softmax<<<B_ROWS / 2, NTHREADS>>>(sf, out);
}

// round 12
// speedup vs baseline: 1.0043x; 1.0043x over previous
#include <cuda_runtime.h>
#include <math.h>

#define B_ROWS   2048
#define NL       64
#define NN       16
#define NO       2048
#define ZSTRIDE  80          // NL + NN
#define TILE_B   64
#define CHUNK_O  128         // A-chunk staged in smem
#define TILE_O   256         // per-block o coverage (2 chunks)
#define MAX_TILES 48
#define NTHREADS 256

// ---------------- device scratch (no allocations allowed) ----------------
__device__ int   g_nid[B_ROWS];
__device__ int   g_order[B_ROWS];
__device__ int   g_bucket_base[NN + 1];
__device__ int   g_tile_bucket[MAX_TILES];
__device__ int   g_tile_start[MAX_TILES];
__device__ int   g_tile_cnt[MAX_TILES];
__device__ int   g_num_tiles;
__device__ float g_logits[(size_t)B_ROWS * NO];   // 16 MB scratch (L2-resident)

// ---------------- packed f32x2 helpers (sm_103a FFMA2 via PTX) ------------
__device__ __forceinline__ void ffma2(unsigned long long& acc,
                                      unsigned long long a,
                                      unsigned long long b)
{
    asm("fma.rn.f32x2 %0, %1, %2, %0;" : "+l"(acc) : "l"(a), "l"(b));
}
__device__ __forceinline__ unsigned long long bcast2(float v)
{
    unsigned long long r;
    asm("mov.b64 %0, {%1, %1};" : "=l"(r) : "f"(v));
    return r;
}
__device__ __forceinline__ float2 unpack2(unsigned long long p)
{
    float2 f;
    asm("mov.b64 {%0, %1}, %2;" : "=f"(f.x), "=f"(f.y) : "l"(p));
    return f;
}

// ---------------- kernel 1: per-row argmax of nuisance one-hot + theta ----
__global__ void k_prep(const float* __restrict__ z,
                       const float* __restrict__ px_r,
                       float* __restrict__ theta_out)
{
    int g = blockIdx.x * blockDim.x + threadIdx.x;
    if (g < B_ROWS) {
        const float* p = z + (size_t)g * ZSTRIDE + NL;
        float best = p[0]; int bi = 0;
        #pragma unroll
        for (int i = 1; i < NN; i++) {
            float v = p[i];
            if (v > best) { best = v; bi = i; }   // first-max wins (jnp.argmax)
        }
        g_nid[g] = bi;
    }
    if (g < NO) theta_out[g] = expf(px_r[g]);
}

// ---------------- kernel 2: counting sort by nid + tile list --------------
__global__ void k_sort()
{
    __shared__ int cnt[NN];
    __shared__ int offs[NN];
    int t = threadIdx.x;
    if (t < NN) cnt[t] = 0;
    __syncthreads();
    for (int b = t; b < B_ROWS; b += blockDim.x)
        atomicAdd(&cnt[g_nid[b]], 1);
    __syncthreads();
    if (t == 0) {
        int acc = 0;
        for (int i = 0; i < NN; i++) {
            g_bucket_base[i] = acc;
            offs[i] = acc;
            acc += cnt[i];
        }
        g_bucket_base[NN] = acc;
    }
    __syncthreads();
    for (int b = t; b < B_ROWS; b += blockDim.x) {
        int p = atomicAdd(&offs[g_nid[b]], 1);
        g_order[p] = b;
    }
    if (t == 0) {
        int nt = 0;
        for (int i = 0; i < NN; i++) {
            int base = g_bucket_base[i];
            int c    = g_bucket_base[i + 1] - base;
            for (int s = 0; s < c; s += TILE_B) {
                g_tile_bucket[nt] = i;
                g_tile_start[nt]  = base + s;
                g_tile_cnt[nt]    = min(TILE_B, c - s);
                nt++;
            }
        }
        g_num_tiles = nt;
    }
}

// Zs is k-major [k][64 rows]; swizzle xors only bits>=2 of r so any aligned
// 4-row group stays contiguous AND in order for LDS.128.
__device__ __forceinline__ int zswz(int r, int k)
{
    return r ^ (((k >> 2) & 7) << 2);
}

// ---------------- kernel 3: bucketed GEMM  logits = Z0 @ (W + S[nid]) + off
// Dynamic smem = 64*64 (Zs, k-major) + 64*128 (As) floats = 49152 B exactly.
// Warp tile 32x32 (warps 2x4), lane tile 4 rows x 8 cols: smem read per warp
// per k = 128B(A) + 128B(z) for 1024 FMA -> 0.25 B/FMA (was 0.53).
__global__ __launch_bounds__(NTHREADS)
void k_gemm(const float* __restrict__ z,
            const float* __restrict__ W,
            const float* __restrict__ S,
            const float* __restrict__ offsets)
{
    int tile = blockIdx.x;
    if (tile >= g_num_tiles) return;

    extern __shared__ float sm[];
    float* Zs = sm;                       // [64 k][64 r] swizzled
    float* As = sm + TILE_B * NL;         // [64 k][128 c]

    int tid    = threadIdx.x;
    int bucket = g_tile_bucket[tile];
    int start  = g_tile_start[tile];
    int vcnt   = g_tile_cnt[tile];

    int w    = tid >> 5;
    int lane = tid & 31;
    int wrow = w & 1;          // 2 row-warps x 32 rows
    int wcol = w >> 1;         // 4 col-warps x 32 cols
    int R    = wrow * 32 + (lane & 7) * 4;   // rows R..R+3
    int C    = wcol * 32 + (lane >> 3) * 8;  // cols C..C+7

    // row indices for this thread's 4 output rows (register-cached)
    int rowidx[4];
    #pragma unroll
    for (int i = 0; i < 4; i++)
        rowidx[i] = (R + i < vcnt) ? g_order[start + R + i] : -1;

    // ---- stage Z k-major swizzled (64 rows x 16 float4 loads) ------------
    {
        #pragma unroll
        for (int j = 0; j < 4; j++) {
            int e  = tid + j * NTHREADS;   // 0..1023
            int r  = e >> 4;
            int l4 = e & 15;
            float4 v = make_float4(0.f, 0.f, 0.f, 0.f);
            if (r < vcnt) {
                int row = g_order[start + r];
                v = *(const float4*)(z + (size_t)row * ZSTRIDE + l4 * 4);
            }
            int k = l4 * 4;
            Zs[(k + 0) * TILE_B + zswz(r, k + 0)] = v.x;
            Zs[(k + 1) * TILE_B + zswz(r, k + 1)] = v.y;
            Zs[(k + 2) * TILE_B + zswz(r, k + 2)] = v.z;
            Zs[(k + 3) * TILE_B + zswz(r, k + 3)] = v.w;
        }
    }

    const float4* W4 = (const float4*)W;
    const float4* S4 = (const float4*)(S + (size_t)bucket * NL * NO);

    #pragma unroll
    for (int chunk = 0; chunk < TILE_O / CHUNK_O; chunk++) {
        int o0 = blockIdx.y * TILE_O + chunk * CHUNK_O;

        __syncthreads();   // Z staged (chunk 0) / prior compute reads done

        // ---- stage A_eff = W + S[bucket] (64 x 128 floats = 2048 float4) --
        {
            int ob4 = o0 >> 2;
            #pragma unroll
            for (int j = 0; j < 8; j++) {
                int e  = tid + j * NTHREADS;   // 0..2047
                int k  = e >> 5;
                int c4 = e & 31;
                float4 wv = W4[(size_t)k * (NO / 4) + ob4 + c4];
                float4 sv = S4[(size_t)k * (NO / 4) + ob4 + c4];
                ((float4*)(As + k * CHUNK_O))[c4] =
                    make_float4(wv.x + sv.x, wv.y + sv.y, wv.z + sv.z, wv.w + sv.w);
            }
        }
        __syncthreads();

        // packed accumulators: acc[i][j] = row R+i, col pair (C+2j, C+2j+1)
        unsigned long long acc[4][4];
        #pragma unroll
        for (int i = 0; i < 4; i++)
            #pragma unroll
            for (int j = 0; j < 4; j++) acc[i][j] = 0ull;

        #pragma unroll 8
        for (int k = 0; k < NL; k++) {
            float4 zf = *(const float4*)(Zs + k * TILE_B + zswz(R, k));
            ulonglong2 a0 = *(const ulonglong2*)(As + k * CHUNK_O + C);
            ulonglong2 a1 = *(const ulonglong2*)(As + k * CHUNK_O + C + 4);
            #pragma unroll
            for (int i = 0; i < 4; i++) {
                unsigned long long zz = bcast2((&zf.x)[i]);
                ffma2(acc[i][0], zz, a0.x);
                ffma2(acc[i][1], zz, a0.y);
                ffma2(acc[i][2], zz, a1.x);
                ffma2(acc[i][3], zz, a1.y);
            }
        }

        // ---- epilogue: + offsets[bucket], scatter rows to logits scratch --
        const float4 offlo = *(const float4*)(offsets + (size_t)bucket * NO + o0 + C);
        const float4 offhi = *(const float4*)(offsets + (size_t)bucket * NO + o0 + C + 4);
        #pragma unroll
        for (int i = 0; i < 4; i++) {
            int row = rowidx[i];
            if (row < 0) continue;
            float2 p0 = unpack2(acc[i][0]);
            float2 p1 = unpack2(acc[i][1]);
            float2 p2 = unpack2(acc[i][2]);
            float2 p3 = unpack2(acc[i][3]);
            float* dst = g_logits + (size_t)row * NO + o0 + C;
            *(float4*)(dst)     = make_float4(p0.x + offlo.x, p0.y + offlo.y,
                                              p1.x + offlo.z, p1.y + offlo.w);
            *(float4*)(dst + 4) = make_float4(p2.x + offhi.x, p2.y + offhi.y,
                                              p3.x + offhi.z, p3.y + offhi.w);
        }
    }
}

// ---------------- kernel 4: row softmax * size_factor (flash, 2 rows/block)
// 128 threads per row; each thread covers 4 float4 = 16 of 2048 elements.
__global__ __launch_bounds__(NTHREADS)
void k_softmax(const float* __restrict__ sf, float* __restrict__ mu)
{
    int tid  = threadIdx.x;
    int half = tid >> 7;                 // 0/1: which row of this block
    int t    = tid & 127;                // position within row (float4 units)
    int b    = blockIdx.x * 2 + half;
    int lane = tid & 31;
    int wid  = tid >> 5;                 // 0..7 (warps 0-3 row0, 4-7 row1)

    const float4* src = (const float4*)g_logits + (size_t)b * (NO / 4);
    float4 v[4];
    #pragma unroll
    for (int q = 0; q < 4; q++) v[q] = src[t + q * 128];

    // per-warp max over this thread's 16 values
    float mx = -1e30f;
    #pragma unroll
    for (int q = 0; q < 4; q++)
        mx = fmaxf(mx, fmaxf(fmaxf(v[q].x, v[q].y), fmaxf(v[q].z, v[q].w)));
    #pragma unroll
    for (int o = 16; o; o >>= 1)
        mx = fmaxf(mx, __shfl_xor_sync(0xffffffffu, mx, o));

    // per-warp sum of exp(v - warp_max)
    float e[16];
    float s = 0.f;
    #pragma unroll
    for (int q = 0; q < 4; q++) {
        e[q * 4 + 0] = __expf(v[q].x - mx);
        e[q * 4 + 1] = __expf(v[q].y - mx);
        e[q * 4 + 2] = __expf(v[q].z - mx);
        e[q * 4 + 3] = __expf(v[q].w - mx);
        s += (e[q * 4 + 0] + e[q * 4 + 1]) + (e[q * 4 + 2] + e[q * 4 + 3]);
    }
    #pragma unroll
    for (int o = 16; o; o >>= 1)
        s += __shfl_xor_sync(0xffffffffu, s, o);

    __shared__ float smax[8];
    __shared__ float ssum[8];
    if (lane == 0) { smax[wid] = mx; ssum[wid] = s; }
    __syncthreads();

    int w0 = half * 4;   // this row's warps: w0..w0+3
    float M = fmaxf(fmaxf(smax[w0], smax[w0 + 1]),
                    fmaxf(smax[w0 + 2], smax[w0 + 3]));
    float Ssum = ssum[w0]     * __expf(smax[w0]     - M)
               + ssum[w0 + 1] * __expf(smax[w0 + 1] - M)
               + ssum[w0 + 2] * __expf(smax[w0 + 2] - M)
               + ssum[w0 + 3] * __expf(smax[w0 + 3] - M);

    // rescale warp-local exps: e * exp(mx - M) / Ssum * sf
    float scale = (sf[b] / Ssum) * __expf(mx - M);

    float4* dst = (float4*)mu + (size_t)b * (NO / 4);
    #pragma unroll
    for (int q = 0; q < 4; q++)
        dst[t + q * 128] = make_float4(e[q * 4 + 0] * scale, e[q * 4 + 1] * scale,
                                       e[q * 4 + 2] * scale, e[q * 4 + 3] * scale);
}

// -------------------------------------------------------------------------
extern "C" void kernel_launch(void* const* d_in, const int* in_sizes, int n_in,
                              void* d_out, int out_size)
{
    const float* z       = (const float*)d_in[0];
    const float* sf      = (const float*)d_in[1];
    const float* W       = (const float*)d_in[2];
    const float* S       = (const float*)d_in[3];
    const float* offsets = (const float*)d_in[4];
    const float* px_r    = (const float*)d_in[5];
    float* out   = (float*)d_out;
    float* theta = out + (out_size - NO);   // layout: mu[B,NO] then theta[NO]

    k_prep<<<(B_ROWS + NTHREADS - 1) / NTHREADS, NTHREADS>>>(z, px_r, theta);
    k_sort<<<1, NTHREADS>>>();

    size_t smem = (size_t)(TILE_B * NL + NL * CHUNK_O) * sizeof(float);  // 49152 B
    k_gemm<<<dim3(MAX_TILES, NO / TILE_O), NTHREADS, smem>>>(z, W, S, offsets);

    k_softmax<<<B_ROWS / 2, NTHREADS>>>(sf, out);
}

// round 13
// speedup vs baseline: 1.0779x; 1.0733x over previous
#include <cuda_runtime.h>
#include <math.h>

#define B_ROWS   2048
#define NL       64
#define NN       16
#define NO       2048
#define ZSTRIDE  80          // NL + NN
#define TILE_B   64
#define CHUNK_O  128         // A-chunk staged in smem
#define TILE_O   256         // per-block o coverage (2 chunks)
#define MAX_TILES 48
#define NTHREADS 256

// ---------------- device scratch (no allocations allowed) ----------------
__device__ int   g_nid[B_ROWS];
__device__ int   g_order[B_ROWS];
__device__ int   g_bucket_base[NN + 1];
__device__ int   g_tile_bucket[MAX_TILES];
__device__ int   g_tile_start[MAX_TILES];
__device__ int   g_tile_cnt[MAX_TILES];
__device__ int   g_num_tiles;
__device__ float g_rowsum[B_ROWS];                // per-row sum of exp(logit)
__device__ float g_logits[(size_t)B_ROWS * NO];   // 16 MB scratch (L2-resident)

// ---------------- packed f32x2 helpers (sm_103a FFMA2 via PTX) ------------
__device__ __forceinline__ void ffma2(unsigned long long& acc,
                                      unsigned long long a,
                                      unsigned long long b)
{
    asm("fma.rn.f32x2 %0, %1, %2, %0;" : "+l"(acc) : "l"(a), "l"(b));
}
__device__ __forceinline__ unsigned long long bcast2(float v)
{
    unsigned long long r;
    asm("mov.b64 %0, {%1, %1};" : "=l"(r) : "f"(v));
    return r;
}
__device__ __forceinline__ float2 unpack2(unsigned long long p)
{
    float2 f;
    asm("mov.b64 {%0, %1}, %2;" : "=f"(f.x), "=f"(f.y) : "l"(p));
    return f;
}

// ---------------- kernel 1: argmax + theta + zero rowsum ------------------
__global__ void k_prep(const float* __restrict__ z,
                       const float* __restrict__ px_r,
                       float* __restrict__ theta_out)
{
    int g = blockIdx.x * blockDim.x + threadIdx.x;
    if (g < B_ROWS) {
        const float* p = z + (size_t)g * ZSTRIDE + NL;
        float best = p[0]; int bi = 0;
        #pragma unroll
        for (int i = 1; i < NN; i++) {
            float v = p[i];
            if (v > best) { best = v; bi = i; }   // first-max wins (jnp.argmax)
        }
        g_nid[g] = bi;
        g_rowsum[g] = 0.f;                        // reset accumulator per launch
    }
    if (g < NO) theta_out[g] = expf(px_r[g]);
}

// ---------------- kernel 2: counting sort by nid + tile list --------------
__global__ void k_sort()
{
    __shared__ int cnt[NN];
    __shared__ int offs[NN];
    int t = threadIdx.x;
    if (t < NN) cnt[t] = 0;
    __syncthreads();
    for (int b = t; b < B_ROWS; b += blockDim.x)
        atomicAdd(&cnt[g_nid[b]], 1);
    __syncthreads();
    if (t == 0) {
        int acc = 0;
        for (int i = 0; i < NN; i++) {
            g_bucket_base[i] = acc;
            offs[i] = acc;
            acc += cnt[i];
        }
        g_bucket_base[NN] = acc;
    }
    __syncthreads();
    for (int b = t; b < B_ROWS; b += blockDim.x) {
        int p = atomicAdd(&offs[g_nid[b]], 1);
        g_order[p] = b;
    }
    if (t == 0) {
        int nt = 0;
        for (int i = 0; i < NN; i++) {
            int base = g_bucket_base[i];
            int c    = g_bucket_base[i + 1] - base;
            for (int s = 0; s < c; s += TILE_B) {
                g_tile_bucket[nt] = i;
                g_tile_start[nt]  = base + s;
                g_tile_cnt[nt]    = min(TILE_B, c - s);
                nt++;
            }
        }
        g_num_tiles = nt;
    }
}

// Z tile swizzle: row-major [r][64], float4-group column c4 (0..15) XORed by
// a bit derived from r so that rows r and r+4 (the two ty-groups of a warp)
// land 16 banks apart. Mainloop loads are LDS.128, conflict-free.
__device__ __forceinline__ int zc4(int r, int c4)
{
    return c4 ^ (((r >> 2) & 1) << 2);
}

// ---------------- kernel 3: bucketed GEMM + exp-sum epilogue --------------
// logits = Z0 @ (W + S[nid]) + off; also atomically accumulates
// g_rowsum[row] += sum_j exp(logit[row][j]) (unnormalized softmax is safe:
// |logit| <~ 41 << 88). Dynamic smem = 49152 B exactly.
__global__ __launch_bounds__(NTHREADS)
void k_gemm(const float* __restrict__ z,
            const float* __restrict__ W,
            const float* __restrict__ S,
            const float* __restrict__ offsets)
{
    int tile = blockIdx.x;
    if (tile >= g_num_tiles) return;

    extern __shared__ float sm[];
    float* Zs = sm;                       // [64][64] row-major, swizzled c4
    float* As = sm + TILE_B * NL;         // [64][128]

    int tid    = threadIdx.x;
    int bucket = g_tile_bucket[tile];
    int start  = g_tile_start[tile];
    int vcnt   = g_tile_cnt[tile];

    int tx = tid & 15;     // col group: cols {tx*4..+3} and {64+tx*4..+3}
    int ty = tid >> 4;     // row group: rows ty*4..+3

    // row indices for this thread's 4 output rows (register-cached)
    int rowidx[4];
    #pragma unroll
    for (int i = 0; i < 4; i++) {
        int r = ty * 4 + i;
        rowidx[i] = (r < vcnt) ? g_order[start + r] : -1;
    }

    // ---- stage Z row-major swizzled (64 rows x 16 float4 = 1024 float4) ----
    {
        #pragma unroll
        for (int j = 0; j < 4; j++) {
            int e  = tid + j * NTHREADS;   // 0..1023
            int r  = e >> 4;
            int l4 = e & 15;
            int row = (r < vcnt) ? g_order[start + r] : -1;
            float4 v = make_float4(0.f, 0.f, 0.f, 0.f);
            if (row >= 0)
                v = *(const float4*)(z + (size_t)row * ZSTRIDE + l4 * 4);
            *(float4*)(Zs + r * NL + zc4(r, l4) * 4) = v;
        }
    }

    const float4* W4 = (const float4*)W;
    const float4* S4 = (const float4*)(S + (size_t)bucket * NL * NO);

    #pragma unroll
    for (int chunk = 0; chunk < TILE_O / CHUNK_O; chunk++) {
        int o0 = blockIdx.y * TILE_O + chunk * CHUNK_O;

        __syncthreads();   // Z stage done (chunk 0) / prior compute reads done

        // ---- stage A_eff = W + S[bucket] (64 x 128 floats = 2048 float4) --
        {
            int ob4 = o0 >> 2;
            #pragma unroll
            for (int j = 0; j < 8; j++) {
                int e  = tid + j * NTHREADS;   // 0..2047
                int k  = e >> 5;
                int c4 = e & 31;
                float4 w = W4[(size_t)k * (NO / 4) + ob4 + c4];
                float4 s = S4[(size_t)k * (NO / 4) + ob4 + c4];
                ((float4*)(As + k * CHUNK_O))[c4] =
                    make_float4(w.x + s.x, w.y + s.y, w.z + s.z, w.w + s.w);
            }
        }
        __syncthreads();

        // packed accumulators: acc[i][j] = (col 2j, col 2j+1) of group
        unsigned long long acc[4][8];
        #pragma unroll
        for (int i = 0; i < 4; i++)
            #pragma unroll
            for (int j = 0; j < 8; j++) acc[i][j] = 0ull;

        #pragma unroll 4
        for (int k4 = 0; k4 < NL; k4 += 4) {
            float4 zq[4];
            #pragma unroll
            for (int i = 0; i < 4; i++) {
                int r = ty * 4 + i;
                zq[i] = *(const float4*)(Zs + r * NL + zc4(r, k4 >> 2) * 4);
            }
            #pragma unroll
            for (int kk = 0; kk < 4; kk++) {
                ulonglong2 a0 = *(const ulonglong2*)(As + (k4 + kk) * CHUNK_O + tx * 4);
                ulonglong2 a1 = *(const ulonglong2*)(As + (k4 + kk) * CHUNK_O + 64 + tx * 4);
                #pragma unroll
                for (int i = 0; i < 4; i++) {
                    unsigned long long zz = bcast2((&zq[i].x)[kk]);
                    ffma2(acc[i][0], zz, a0.x);
                    ffma2(acc[i][1], zz, a0.y);
                    ffma2(acc[i][2], zz, a1.x);
                    ffma2(acc[i][3], zz, a1.y);
                }
            }
        }

        // ---- epilogue: + offsets, store logits, accumulate exp-sums -------
        const float4 offlo = *(const float4*)(offsets + (size_t)bucket * NO + o0 + tx * 4);
        const float4 offhi = *(const float4*)(offsets + (size_t)bucket * NO + o0 + 64 + tx * 4);
        #pragma unroll
        for (int i = 0; i < 4; i++) {
            int row = rowidx[i];   // uniform across the 16-lane tx-group
            float2 p0 = unpack2(acc[i][0]);
            float2 p1 = unpack2(acc[i][1]);
            float2 p2 = unpack2(acc[i][2]);
            float2 p3 = unpack2(acc[i][3]);
            float4 olo = make_float4(p0.x + offlo.x, p0.y + offlo.y,
                                     p1.x + offlo.z, p1.y + offlo.w);
            float4 ohi = make_float4(p2.x + offhi.x, p2.y + offhi.y,
                                     p3.x + offhi.z, p3.y + offhi.w);
            float rs = 0.f;
            if (row >= 0) {
                float* dst = g_logits + (size_t)row * NO + o0;
                *(float4*)(dst + tx * 4)      = olo;
                *(float4*)(dst + 64 + tx * 4) = ohi;
                rs = ((__expf(olo.x) + __expf(olo.y)) + (__expf(olo.z) + __expf(olo.w)))
                   + ((__expf(ohi.x) + __expf(ohi.y)) + (__expf(ohi.z) + __expf(ohi.w)));
            }
            // reduce across the 16-lane tx-group (bits 0-3 of lane id)
            rs += __shfl_xor_sync(0xffffffffu, rs, 8);
            rs += __shfl_xor_sync(0xffffffffu, rs, 4);
            rs += __shfl_xor_sync(0xffffffffu, rs, 2);
            rs += __shfl_xor_sync(0xffffffffu, rs, 1);
            if (tx == 0 && row >= 0)
                atomicAdd(&g_rowsum[row], rs);
        }
    }
}

// ---------------- kernel 4: elementwise scale  mu = exp(l)*sf/rowsum ------
// 2 rows per 256-thread block; no barriers, no reductions, pure stream.
__global__ __launch_bounds__(NTHREADS)
void k_scale(const float* __restrict__ sf, float* __restrict__ mu)
{
    int tid  = threadIdx.x;
    int half = tid >> 7;                 // 0/1: which row of this block
    int t    = tid & 127;                // position within row (float4 units)
    int b    = blockIdx.x * 2 + half;

    float scale = sf[b] / g_rowsum[b];

    const float4* src = (const float4*)g_logits + (size_t)b * (NO / 4);
    float4*       dst = (float4*)mu + (size_t)b * (NO / 4);
    #pragma unroll
    for (int q = 0; q < 4; q++) {
        float4 v = src[t + q * 128];
        dst[t + q * 128] = make_float4(__expf(v.x) * scale, __expf(v.y) * scale,
                                       __expf(v.z) * scale, __expf(v.w) * scale);
    }
}

// -------------------------------------------------------------------------
extern "C" void kernel_launch(void* const* d_in, const int* in_sizes, int n_in,
                              void* d_out, int out_size)
{
    const float* z       = (const float*)d_in[0];
    const float* sf      = (const float*)d_in[1];
    const float* W       = (const float*)d_in[2];
    const float* S       = (const float*)d_in[3];
    const float* offsets = (const float*)d_in[4];
    const float* px_r    = (const float*)d_in[5];
    float* out   = (float*)d_out;
    float* theta = out + (out_size - NO);   // layout: mu[B,NO] then theta[NO]

    k_prep<<<(B_ROWS + NTHREADS - 1) / NTHREADS, NTHREADS>>>(z, px_r, theta);
    k_sort<<<1, NTHREADS>>>();

    size_t smem = (size_t)(TILE_B * NL + NL * CHUNK_O) * sizeof(float);  // 49152 B
    k_gemm<<<dim3(MAX_TILES, NO / TILE_O), NTHREADS, smem>>>(z, W, S, offsets);

    k_scale<<<B_ROWS / 2, NTHREADS>>>(sf, out);
}